// round 13
// baseline (speedup 1.0000x reference)
#include <cuda_runtime.h>
#include <cuda_fp16.h>
#include <cstdint>

// ---------------------------------------------------------------------------
// MaxViT3D MHSA (round 13): fp16 mma pipeline.
//   vs round 12 (261.9us):
//   - all 4 prep kernels fused into ONE (block-range dispatch) -> prep time
//     ~= max(component) instead of sum(components) + launch gaps
//   - attention K/V staging vectorized to half2 LDGs (was 2-byte LDG.U16)
//   GEMMs and attention chunk loop byte-identical to round 12.
// ---------------------------------------------------------------------------

#define NWIN 128
#define NT   343
#define NTP  352
#define NTB  352
#define D    256
#define H    8
#define DH   32

// scratch
__device__ __half g_qkvh  [(size_t)NWIN * NT * (3 * D)];
__device__ __half g_ctxh  [(size_t)NWIN * NT * D];
__device__ __half g_xh    [(size_t)NWIN * NT * D];
__device__ __half g_wqkvTh[(size_t)(3 * D) * D];   // W_qkv^T [768][256] K-major
__device__ __half g_woutTh[(size_t)D * D];         // W_out^T [256][256] K-major
__device__ __half g_biash [(size_t)H * NT * NTB];

// ---------------------------------------------------------------------------
// helpers
// ---------------------------------------------------------------------------
__device__ __forceinline__ void mma16(float* c, const unsigned* a,
                                      unsigned b0, unsigned b1) {
    asm volatile(
        "mma.sync.aligned.m16n8k16.row.col.f32.f16.f16.f32 "
        "{%0,%1,%2,%3},{%4,%5,%6,%7},{%8,%9},{%0,%1,%2,%3};"
        : "+f"(c[0]), "+f"(c[1]), "+f"(c[2]), "+f"(c[3])
        : "r"(a[0]), "r"(a[1]), "r"(a[2]), "r"(a[3]), "r"(b0), "r"(b1));
}

__device__ __forceinline__ unsigned smem_u32(const void* p) {
    unsigned r;
    asm("{.reg .u64 t; cvta.to.shared.u64 t, %1; cvt.u32.u64 %0, t;}"
        : "=r"(r) : "l"(p));
    return r;
}

__device__ __forceinline__ void cpa16(unsigned dst, const void* src) {
    asm volatile("cp.async.ca.shared.global [%0], [%1], 16;" :: "r"(dst), "l"(src));
}
#define CP_COMMIT() asm volatile("cp.async.commit_group;")

// ---------------------------------------------------------------------------
// fused prep kernel: x->half, W_qkv^T->half, W_out^T->half, bias->half
// block ranges: [0,XB) x-convert; [XB,XB+QB) wqkv; [..,+OB) wout; rest bias
// ---------------------------------------------------------------------------
#define PREP_XB 10976   // (128*343*256/4) / 256
#define PREP_QB 768     // (768*256) / 256
#define PREP_OB 256     // (256*256) / 256
#define PREP_BB 3773    // (8*343*352) / 256
#define PREP_GRID (PREP_XB + PREP_QB + PREP_OB + PREP_BB)

__global__ void prep_kernel(const float4* __restrict__ x,
                            const float* __restrict__ wqkv,
                            const float* __restrict__ wout,
                            const float* __restrict__ table) {
    const int b = blockIdx.x;
    if (b < PREP_XB) {
        int i = b * 256 + threadIdx.x;             // over n4x
        float4 v = x[i];
        __half2 h0 = __floats2half2_rn(v.x, v.y);
        __half2 h1 = __floats2half2_rn(v.z, v.w);
        ((uint2*)g_xh)[i] = make_uint2(*(unsigned*)&h0, *(unsigned*)&h1);
    } else if (b < PREP_XB + PREP_QB) {
        int idx = (b - PREP_XB) * 256 + threadIdx.x;   // over [768][256]
        int n = idx >> 8, k = idx & 255;
        g_wqkvTh[idx] = __float2half_rn(wqkv[k * (3 * D) + n]);
    } else if (b < PREP_XB + PREP_QB + PREP_OB) {
        int idx = (b - PREP_XB - PREP_QB) * 256 + threadIdx.x;  // [256][256]
        int n = idx >> 8, k = idx & 255;
        g_woutTh[idx] = __float2half_rn(wout[k * D + n]);
    } else {
        int idx = (b - PREP_XB - PREP_QB - PREP_OB) * 256 + threadIdx.x;
        int h = idx / (NT * NTB);
        int r = idx - h * (NT * NTB);
        int i = r / NTB;
        int j = r - i * NTB;
        float v = 0.0f;
        if (j < NT) {
            int i1 = i / 49, i2 = (i / 7) % 7, i3 = i % 7;
            int j1 = j / 49, j2 = (j / 7) % 7, j3 = j % 7;
            int rel = ((i1 - j1 + 6) * 13 + (i2 - j2 + 6)) * 13 + (i3 - j3 + 6);
            v = table[rel * H + h];
        }
        g_biash[idx] = __float2half_rn(v);
    }
}

// ---------------------------------------------------------------------------
// fp16 GEMM (unchanged from round 12)
// ---------------------------------------------------------------------------
#define LGH 40   // smem row stride in halfs

__device__ __forceinline__ void stage32(unsigned dstBase,
                                        const __half* __restrict__ gsrc) {
    const int tid = threadIdx.x;
#pragma unroll
    for (int i = 0; i < 2; i++) {
        int id  = tid + i * 256;
        int row = id >> 2;
        int gc  = (id & 3) * 8;            // 8 halfs = 16B granule
        cpa16(dstBase + (unsigned)(row * LGH + gc) * 2,
              gsrc + (size_t)row * 256 + gc);
    }
}

template <bool HALF_OUT>
__device__ __forceinline__ void fp16_gemm_body(const __half* __restrict__ Ag,
                                               const __half* __restrict__ Bg,
                                               float* __restrict__ Cf,
                                               __half* __restrict__ Ch,
                                               int Ngl) {
    __shared__ __half As[2][128 * LGH];
    __shared__ __half Bs[2][128 * LGH];

    const int tid  = threadIdx.x;
    const int warp = tid >> 5, lane = tid & 31;
    const int g = lane >> 2, t = lane & 3;
    const int wm = warp >> 2, wn = warp & 3;

    const int rowBase = blockIdx.y * 128;
    const int colBase = blockIdx.x * 128;

    const __half* Ab = Ag + (size_t)rowBase * 256;
    const __half* Bb = Bg + (size_t)colBase * 256;

    const unsigned asb0 = smem_u32(&As[0][0]);
    const unsigned bsb0 = smem_u32(&Bs[0][0]);
    const unsigned bufBytes = 128 * LGH * 2;

    float acc[4][4][4];
#pragma unroll
    for (int mt = 0; mt < 4; mt++)
#pragma unroll
        for (int nt = 0; nt < 4; nt++)
#pragma unroll
            for (int i = 0; i < 4; i++) acc[mt][nt][i] = 0.0f;

    stage32(asb0, Ab);
    stage32(bsb0, Bb);
    CP_COMMIT();

    const int iters = 256 / 32;   // 8
    for (int it = 0; it < iters; it++) {
        asm volatile("cp.async.wait_group 0;" ::: "memory");
        __syncthreads();
        if (it + 1 < iters) {
            int nb = (it + 1) & 1;
            stage32(asb0 + nb * bufBytes, Ab + (it + 1) * 32);
            stage32(bsb0 + nb * bufBytes, Bb + (it + 1) * 32);
            CP_COMMIT();
        }
        const __half* Abs = As[it & 1];
        const __half* Bbs = Bs[it & 1];

#pragma unroll
        for (int ks = 0; ks < 32; ks += 16) {
            unsigned a[4][4], b[4][2];
#pragma unroll
            for (int mt = 0; mt < 4; mt++) {
                int r = wm * 64 + mt * 16;
                a[mt][0] = *(const unsigned*)&Abs[(r + g)     * LGH + ks + 2 * t];
                a[mt][1] = *(const unsigned*)&Abs[(r + g + 8) * LGH + ks + 2 * t];
                a[mt][2] = *(const unsigned*)&Abs[(r + g)     * LGH + ks + 2 * t + 8];
                a[mt][3] = *(const unsigned*)&Abs[(r + g + 8) * LGH + ks + 2 * t + 8];
            }
#pragma unroll
            for (int nt = 0; nt < 4; nt++) {
                int cb = wn * 32 + nt * 8;
                b[nt][0] = *(const unsigned*)&Bbs[(cb + g) * LGH + ks + 2 * t];
                b[nt][1] = *(const unsigned*)&Bbs[(cb + g) * LGH + ks + 2 * t + 8];
            }
#pragma unroll
            for (int mt = 0; mt < 4; mt++)
#pragma unroll
                for (int nt = 0; nt < 4; nt++)
                    mma16(acc[mt][nt], a[mt], b[nt][0], b[nt][1]);
        }
    }

#pragma unroll
    for (int mt = 0; mt < 4; mt++) {
#pragma unroll
        for (int nt = 0; nt < 4; nt++) {
            int r = rowBase + wm * 64 + mt * 16 + g;
            int c = colBase + wn * 32 + nt * 8 + 2 * t;
            if (HALF_OUT) {
                __half2 h0 = __floats2half2_rn(acc[mt][nt][0], acc[mt][nt][1]);
                __half2 h1 = __floats2half2_rn(acc[mt][nt][2], acc[mt][nt][3]);
                *(__half2*)(Ch + (size_t)r * Ngl + c)       = h0;
                *(__half2*)(Ch + (size_t)(r + 8) * Ngl + c) = h1;
            } else {
                *(float2*)(Cf + (size_t)r * Ngl + c) =
                    make_float2(acc[mt][nt][0], acc[mt][nt][1]);
                *(float2*)(Cf + (size_t)(r + 8) * Ngl + c) =
                    make_float2(acc[mt][nt][2], acc[mt][nt][3]);
            }
        }
    }
}

__global__ __launch_bounds__(256)
void k_gemm_qkv() {
    fp16_gemm_body<true>(g_xh, g_wqkvTh, nullptr, g_qkvh, 3 * D);
}

__global__ __launch_bounds__(256)
void k_gemm_out(float* __restrict__ out) {
    fp16_gemm_body<false>(g_ctxh, g_woutTh, out, nullptr, D);
}

// ---------------------------------------------------------------------------
// attention: block = (window, head), 11 warps, fp16 fragments
// (round-12 body; only the K/V staging loop vectorized to half2 LDGs)
// ---------------------------------------------------------------------------
#define LDKH 40
#define LDVH 360
#define LDPH 24
#define AWARPS 11
#define ATHREADS (AWARPS * 32)

__global__ __launch_bounds__(ATHREADS)
void attn_kernel() {
    const int win = blockIdx.x;
    const int h   = blockIdx.y;

    extern __shared__ __half smh[];
    __half* ks = smh;                         // NTP*LDKH
    __half* vt = ks + NTP * LDKH;             // 32*LDVH
    __half* pb = vt + 32 * LDVH;              // AWARPS*16*LDPH

    const int tid  = threadIdx.x;
    const int warp = tid >> 5, lane = tid & 31;
    const int g = lane >> 2, t = lane & 3;

    const __half* baseh = g_qkvh + (size_t)win * NT * (3 * D);

    // stage K [j][c] and V^T [c][j] with half2 global loads
    {
        const __half2 z2 = __floats2half2_rn(0.0f, 0.0f);
        for (int idx = tid; idx < NTP * DH / 2; idx += ATHREADS) {
            int j  = idx >> 4;                 // 16 half2 per row
            int c2 = (idx & 15) * 2;           // even column
            __half2 kv = z2, vv = z2;
            if (j < NT) {
                const __half* row = baseh + (size_t)j * (3 * D) + h * DH;
                kv = *(const __half2*)(row + D + c2);
                vv = *(const __half2*)(row + 2 * D + c2);
            }
            *(__half2*)&ks[j * LDKH + c2] = kv;
            vt[c2 * LDVH + j]       = __low2half(vv);
            vt[(c2 + 1) * LDVH + j] = __high2half(vv);
        }
    }
    __syncthreads();

    const float scale = 0.17677669529663687f;
    const __half* bh = g_biash + (size_t)h * NT * NTB;
    __half* pw = pb + warp * 16 * LDPH;

    for (int qt = warp; qt < 22; qt += AWARPS) {
        const int i0 = qt * 16;
        const int r1 = i0 + g, r2 = r1 + 8;
        const int r1c = r1 < NT ? r1 : NT - 1;
        const int r2c = r2 < NT ? r2 : NT - 1;

        unsigned qa[2][4];
        const __half* q1p = baseh + (size_t)r1c * (3 * D) + h * DH;
        const __half* q2p = baseh + (size_t)r2c * (3 * D) + h * DH;
#pragma unroll
        for (int kk = 0; kk < 2; kk++) {
            qa[kk][0] = *(const unsigned*)(q1p + kk * 16 + 2 * t);
            qa[kk][1] = *(const unsigned*)(q2p + kk * 16 + 2 * t);
            qa[kk][2] = *(const unsigned*)(q1p + kk * 16 + 2 * t + 8);
            qa[kk][3] = *(const unsigned*)(q2p + kk * 16 + 2 * t + 8);
        }

        float o[4][4];
#pragma unroll
        for (int ct = 0; ct < 4; ct++)
#pragma unroll
            for (int i = 0; i < 4; i++) o[ct][i] = 0.0f;
        float l1 = 0.0f, l2 = 0.0f;

        const __half* b1p = bh + (size_t)r1c * NTB;
        const __half* b2p = bh + (size_t)r2c * NTB;

        for (int cc = 0; cc < 22; cc++) {
            const int j0 = cc * 16;

            // ---- QK^T: 16x16 S chunk, 4 mmas ----
            float s0[4] = {0, 0, 0, 0}, s1[4] = {0, 0, 0, 0};
#pragma unroll
            for (int kk = 0; kk < 2; kk++) {
                unsigned b0a = *(const unsigned*)&ks[(j0 + g)     * LDKH + kk * 16 + 2 * t];
                unsigned b0b = *(const unsigned*)&ks[(j0 + g)     * LDKH + kk * 16 + 2 * t + 8];
                unsigned b1a = *(const unsigned*)&ks[(j0 + 8 + g) * LDKH + kk * 16 + 2 * t];
                unsigned b1b = *(const unsigned*)&ks[(j0 + 8 + g) * LDKH + kk * 16 + 2 * t + 8];
                mma16(s0, qa[kk], b0a, b0b);
                mma16(s1, qa[kk], b1a, b1b);
            }

            // ---- bias (half2 loads) + exp ----
            const int c0 = j0 + 2 * t;
            float2 b1a = __half22float2(*(const __half2*)(b1p + c0));
            float2 b1b = __half22float2(*(const __half2*)(b1p + c0 + 8));
            float2 b2a = __half22float2(*(const __half2*)(b2p + c0));
            float2 b2b = __half22float2(*(const __half2*)(b2p + c0 + 8));

            float p1[4], p2[4];
            p1[0] = (c0     < NT) ? __expf(fmaf(s0[0], scale, b1a.x)) : 0.0f;
            p1[1] = (c0 + 1 < NT) ? __expf(fmaf(s0[1], scale, b1a.y)) : 0.0f;
            p1[2] = (c0 + 8 < NT) ? __expf(fmaf(s1[0], scale, b1b.x)) : 0.0f;
            p1[3] = (c0 + 9 < NT) ? __expf(fmaf(s1[1], scale, b1b.y)) : 0.0f;
            p2[0] = (c0     < NT) ? __expf(fmaf(s0[2], scale, b2a.x)) : 0.0f;
            p2[1] = (c0 + 1 < NT) ? __expf(fmaf(s0[3], scale, b2a.y)) : 0.0f;
            p2[2] = (c0 + 8 < NT) ? __expf(fmaf(s1[2], scale, b2b.x)) : 0.0f;
            p2[3] = (c0 + 9 < NT) ? __expf(fmaf(s1[3], scale, b2b.y)) : 0.0f;

            l1 += p1[0] + p1[1] + p1[2] + p1[3];
            l2 += p2[0] + p2[1] + p2[2] + p2[3];

            // ---- publish P chunk as half2 (4 STS.32) ----
            *(__half2*)&pw[g * LDPH + 2 * t]           = __floats2half2_rn(p1[0], p1[1]);
            *(__half2*)&pw[g * LDPH + 2 * t + 8]       = __floats2half2_rn(p1[2], p1[3]);
            *(__half2*)&pw[(g + 8) * LDPH + 2 * t]     = __floats2half2_rn(p2[0], p2[1]);
            *(__half2*)&pw[(g + 8) * LDPH + 2 * t + 8] = __floats2half2_rn(p2[2], p2[3]);
            __syncwarp();

            // ---- PV: k16 = whole chunk, 4 mmas ----
            unsigned pa[4];
            pa[0] = *(const unsigned*)&pw[g * LDPH + 2 * t];
            pa[1] = *(const unsigned*)&pw[(g + 8) * LDPH + 2 * t];
            pa[2] = *(const unsigned*)&pw[g * LDPH + 2 * t + 8];
            pa[3] = *(const unsigned*)&pw[(g + 8) * LDPH + 2 * t + 8];
#pragma unroll
            for (int ct = 0; ct < 4; ct++) {
                unsigned b0 = *(const unsigned*)&vt[(ct * 8 + g) * LDVH + j0 + 2 * t];
                unsigned b1 = *(const unsigned*)&vt[(ct * 8 + g) * LDVH + j0 + 2 * t + 8];
                mma16(o[ct], pa, b0, b1);
            }
            __syncwarp();
        }

        l1 += __shfl_xor_sync(0xffffffffu, l1, 1);
        l1 += __shfl_xor_sync(0xffffffffu, l1, 2);
        l2 += __shfl_xor_sync(0xffffffffu, l2, 1);
        l2 += __shfl_xor_sync(0xffffffffu, l2, 2);
        const float inv1 = 1.0f / l1;
        const float inv2 = 1.0f / l2;

        if (r1 < NT) {
            __half* c1 = g_ctxh + ((size_t)win * NT + r1) * D + h * DH;
#pragma unroll
            for (int ct = 0; ct < 4; ct++)
                *(__half2*)(c1 + ct * 8 + 2 * t) =
                    __floats2half2_rn(o[ct][0] * inv1, o[ct][1] * inv1);
        }
        if (r2 < NT) {
            __half* c2 = g_ctxh + ((size_t)win * NT + r2) * D + h * DH;
#pragma unroll
            for (int ct = 0; ct < 4; ct++)
                *(__half2*)(c2 + ct * 8 + 2 * t) =
                    __floats2half2_rn(o[ct][2] * inv2, o[ct][3] * inv2);
        }
    }
}

// ---------------------------------------------------------------------------
// launch
// ---------------------------------------------------------------------------
extern "C" void kernel_launch(void* const* d_in, const int* in_sizes, int n_in,
                              void* d_out, int out_size) {
    const float* x     = (const float*)d_in[0];
    const float* w_qkv = (const float*)d_in[1];
    const float* w_out = (const float*)d_in[2];
    const float* table = (const float*)d_in[3];
    float* out = (float*)d_out;

    const int attn_smem = (NTP * LDKH + 32 * LDVH + AWARPS * 16 * LDPH)
                          * (int)sizeof(__half);
    static int configured = -1;
    if (configured < 0) {
        cudaFuncSetAttribute(attn_kernel,
                             cudaFuncAttributeMaxDynamicSharedMemorySize, attn_smem);
        configured = 1;
    }

    {
        prep_kernel<<<PREP_GRID, 256>>>((const float4*)x, w_qkv, w_out, table);
    }
    {
        dim3 grid(3 * D / 128, (NWIN * NT) / 128);   // (6, 343)
        k_gemm_qkv<<<grid, 256>>>();
    }
    {
        dim3 grid(NWIN, H);
        attn_kernel<<<grid, ATHREADS, attn_smem>>>();
    }
    {
        dim3 grid(D / 128, (NWIN * NT) / 128);       // (2, 343)
        k_gemm_out<<<grid, 256>>>(out);
    }
}

// round 14
// speedup vs baseline: 1.5223x; 1.5223x over previous
#include <cuda_runtime.h>
#include <cuda_fp16.h>
#include <cstdint>

// ---------------------------------------------------------------------------
// MaxViT3D MHSA (round 14): fp16 mma pipeline.
//   = round-12 code (261.9us best) + ONLY the fused prep kernel.
//   Round-13's attention K/V staging rewrite REVERTED (prime regression
//   suspect: every attention-body edit except half-bias has regressed).
// ---------------------------------------------------------------------------

#define NWIN 128
#define NT   343
#define NTP  352
#define NTB  352
#define D    256
#define H    8
#define DH   32

// scratch
__device__ __half g_qkvh  [(size_t)NWIN * NT * (3 * D)];
__device__ __half g_ctxh  [(size_t)NWIN * NT * D];
__device__ __half g_xh    [(size_t)NWIN * NT * D];
__device__ __half g_wqkvTh[(size_t)(3 * D) * D];   // W_qkv^T [768][256] K-major
__device__ __half g_woutTh[(size_t)D * D];         // W_out^T [256][256] K-major
__device__ __half g_biash [(size_t)H * NT * NTB];

// ---------------------------------------------------------------------------
// helpers
// ---------------------------------------------------------------------------
__device__ __forceinline__ void mma16(float* c, const unsigned* a,
                                      unsigned b0, unsigned b1) {
    asm volatile(
        "mma.sync.aligned.m16n8k16.row.col.f32.f16.f16.f32 "
        "{%0,%1,%2,%3},{%4,%5,%6,%7},{%8,%9},{%0,%1,%2,%3};"
        : "+f"(c[0]), "+f"(c[1]), "+f"(c[2]), "+f"(c[3])
        : "r"(a[0]), "r"(a[1]), "r"(a[2]), "r"(a[3]), "r"(b0), "r"(b1));
}

__device__ __forceinline__ unsigned smem_u32(const void* p) {
    unsigned r;
    asm("{.reg .u64 t; cvta.to.shared.u64 t, %1; cvt.u32.u64 %0, t;}"
        : "=r"(r) : "l"(p));
    return r;
}

__device__ __forceinline__ void cpa16(unsigned dst, const void* src) {
    asm volatile("cp.async.ca.shared.global [%0], [%1], 16;" :: "r"(dst), "l"(src));
}
#define CP_COMMIT() asm volatile("cp.async.commit_group;")

// ---------------------------------------------------------------------------
// fused prep kernel: x->half, W_qkv^T->half, W_out^T->half, bias->half
// ---------------------------------------------------------------------------
#define PREP_XB 10976   // (128*343*256/4) / 256
#define PREP_QB 768     // (768*256) / 256
#define PREP_OB 256     // (256*256) / 256
#define PREP_BB 3773    // (8*343*352) / 256
#define PREP_GRID (PREP_XB + PREP_QB + PREP_OB + PREP_BB)

__global__ void prep_kernel(const float4* __restrict__ x,
                            const float* __restrict__ wqkv,
                            const float* __restrict__ wout,
                            const float* __restrict__ table) {
    const int b = blockIdx.x;
    if (b < PREP_XB) {
        int i = b * 256 + threadIdx.x;
        float4 v = x[i];
        __half2 h0 = __floats2half2_rn(v.x, v.y);
        __half2 h1 = __floats2half2_rn(v.z, v.w);
        ((uint2*)g_xh)[i] = make_uint2(*(unsigned*)&h0, *(unsigned*)&h1);
    } else if (b < PREP_XB + PREP_QB) {
        int idx = (b - PREP_XB) * 256 + threadIdx.x;   // over [768][256]
        int n = idx >> 8, k = idx & 255;
        g_wqkvTh[idx] = __float2half_rn(wqkv[k * (3 * D) + n]);
    } else if (b < PREP_XB + PREP_QB + PREP_OB) {
        int idx = (b - PREP_XB - PREP_QB) * 256 + threadIdx.x;  // [256][256]
        int n = idx >> 8, k = idx & 255;
        g_woutTh[idx] = __float2half_rn(wout[k * D + n]);
    } else {
        int idx = (b - PREP_XB - PREP_QB - PREP_OB) * 256 + threadIdx.x;
        int h = idx / (NT * NTB);
        int r = idx - h * (NT * NTB);
        int i = r / NTB;
        int j = r - i * NTB;
        float v = 0.0f;
        if (j < NT) {
            int i1 = i / 49, i2 = (i / 7) % 7, i3 = i % 7;
            int j1 = j / 49, j2 = (j / 7) % 7, j3 = j % 7;
            int rel = ((i1 - j1 + 6) * 13 + (i2 - j2 + 6)) * 13 + (i3 - j3 + 6);
            v = table[rel * H + h];
        }
        g_biash[idx] = __float2half_rn(v);
    }
}

// ---------------------------------------------------------------------------
// fp16 GEMM (unchanged from round 12)
// ---------------------------------------------------------------------------
#define LGH 40   // smem row stride in halfs

__device__ __forceinline__ void stage32(unsigned dstBase,
                                        const __half* __restrict__ gsrc) {
    const int tid = threadIdx.x;
#pragma unroll
    for (int i = 0; i < 2; i++) {
        int id  = tid + i * 256;
        int row = id >> 2;
        int gc  = (id & 3) * 8;            // 8 halfs = 16B granule
        cpa16(dstBase + (unsigned)(row * LGH + gc) * 2,
              gsrc + (size_t)row * 256 + gc);
    }
}

template <bool HALF_OUT>
__device__ __forceinline__ void fp16_gemm_body(const __half* __restrict__ Ag,
                                               const __half* __restrict__ Bg,
                                               float* __restrict__ Cf,
                                               __half* __restrict__ Ch,
                                               int Ngl) {
    __shared__ __half As[2][128 * LGH];
    __shared__ __half Bs[2][128 * LGH];

    const int tid  = threadIdx.x;
    const int warp = tid >> 5, lane = tid & 31;
    const int g = lane >> 2, t = lane & 3;
    const int wm = warp >> 2, wn = warp & 3;

    const int rowBase = blockIdx.y * 128;
    const int colBase = blockIdx.x * 128;

    const __half* Ab = Ag + (size_t)rowBase * 256;
    const __half* Bb = Bg + (size_t)colBase * 256;

    const unsigned asb0 = smem_u32(&As[0][0]);
    const unsigned bsb0 = smem_u32(&Bs[0][0]);
    const unsigned bufBytes = 128 * LGH * 2;

    float acc[4][4][4];
#pragma unroll
    for (int mt = 0; mt < 4; mt++)
#pragma unroll
        for (int nt = 0; nt < 4; nt++)
#pragma unroll
            for (int i = 0; i < 4; i++) acc[mt][nt][i] = 0.0f;

    stage32(asb0, Ab);
    stage32(bsb0, Bb);
    CP_COMMIT();

    const int iters = 256 / 32;   // 8
    for (int it = 0; it < iters; it++) {
        asm volatile("cp.async.wait_group 0;" ::: "memory");
        __syncthreads();
        if (it + 1 < iters) {
            int nb = (it + 1) & 1;
            stage32(asb0 + nb * bufBytes, Ab + (it + 1) * 32);
            stage32(bsb0 + nb * bufBytes, Bb + (it + 1) * 32);
            CP_COMMIT();
        }
        const __half* Abs = As[it & 1];
        const __half* Bbs = Bs[it & 1];

#pragma unroll
        for (int ks = 0; ks < 32; ks += 16) {
            unsigned a[4][4], b[4][2];
#pragma unroll
            for (int mt = 0; mt < 4; mt++) {
                int r = wm * 64 + mt * 16;
                a[mt][0] = *(const unsigned*)&Abs[(r + g)     * LGH + ks + 2 * t];
                a[mt][1] = *(const unsigned*)&Abs[(r + g + 8) * LGH + ks + 2 * t];
                a[mt][2] = *(const unsigned*)&Abs[(r + g)     * LGH + ks + 2 * t + 8];
                a[mt][3] = *(const unsigned*)&Abs[(r + g + 8) * LGH + ks + 2 * t + 8];
            }
#pragma unroll
            for (int nt = 0; nt < 4; nt++) {
                int cb = wn * 32 + nt * 8;
                b[nt][0] = *(const unsigned*)&Bbs[(cb + g) * LGH + ks + 2 * t];
                b[nt][1] = *(const unsigned*)&Bbs[(cb + g) * LGH + ks + 2 * t + 8];
            }
#pragma unroll
            for (int mt = 0; mt < 4; mt++)
#pragma unroll
                for (int nt = 0; nt < 4; nt++)
                    mma16(acc[mt][nt], a[mt], b[nt][0], b[nt][1]);
        }
    }

#pragma unroll
    for (int mt = 0; mt < 4; mt++) {
#pragma unroll
        for (int nt = 0; nt < 4; nt++) {
            int r = rowBase + wm * 64 + mt * 16 + g;
            int c = colBase + wn * 32 + nt * 8 + 2 * t;
            if (HALF_OUT) {
                __half2 h0 = __floats2half2_rn(acc[mt][nt][0], acc[mt][nt][1]);
                __half2 h1 = __floats2half2_rn(acc[mt][nt][2], acc[mt][nt][3]);
                *(__half2*)(Ch + (size_t)r * Ngl + c)       = h0;
                *(__half2*)(Ch + (size_t)(r + 8) * Ngl + c) = h1;
            } else {
                *(float2*)(Cf + (size_t)r * Ngl + c) =
                    make_float2(acc[mt][nt][0], acc[mt][nt][1]);
                *(float2*)(Cf + (size_t)(r + 8) * Ngl + c) =
                    make_float2(acc[mt][nt][2], acc[mt][nt][3]);
            }
        }
    }
}

__global__ __launch_bounds__(256)
void k_gemm_qkv() {
    fp16_gemm_body<true>(g_xh, g_wqkvTh, nullptr, g_qkvh, 3 * D);
}

__global__ __launch_bounds__(256)
void k_gemm_out(float* __restrict__ out) {
    fp16_gemm_body<false>(g_ctxh, g_woutTh, out, nullptr, D);
}

// ---------------------------------------------------------------------------
// attention: block = (window, head), 11 warps, fp16 fragments
// (EXACT round-12 body, including scalar K/V staging)
// ---------------------------------------------------------------------------
#define LDKH 40
#define LDVH 360
#define LDPH 24
#define AWARPS 11
#define ATHREADS (AWARPS * 32)

__global__ __launch_bounds__(ATHREADS)
void attn_kernel() {
    const int win = blockIdx.x;
    const int h   = blockIdx.y;

    extern __shared__ __half smh[];
    __half* ks = smh;                         // NTP*LDKH
    __half* vt = ks + NTP * LDKH;             // 32*LDVH
    __half* pb = vt + 32 * LDVH;              // AWARPS*16*LDPH

    const int tid  = threadIdx.x;
    const int warp = tid >> 5, lane = tid & 31;
    const int g = lane >> 2, t = lane & 3;

    const __half* baseh = g_qkvh + (size_t)win * NT * (3 * D);

    for (int idx = tid; idx < NTP * DH; idx += ATHREADS) {
        int j = idx >> 5, c = idx & 31;
        __half kv = __float2half_rn(0.0f), vv = kv;
        if (j < NT) {
            const __half* row = baseh + (size_t)j * (3 * D) + h * DH;
            kv = row[D + c];
            vv = row[2 * D + c];
        }
        ks[j * LDKH + c] = kv;
        vt[c * LDVH + j] = vv;
    }
    __syncthreads();

    const float scale = 0.17677669529663687f;
    const __half* bh = g_biash + (size_t)h * NT * NTB;
    __half* pw = pb + warp * 16 * LDPH;

    for (int qt = warp; qt < 22; qt += AWARPS) {
        const int i0 = qt * 16;
        const int r1 = i0 + g, r2 = r1 + 8;
        const int r1c = r1 < NT ? r1 : NT - 1;
        const int r2c = r2 < NT ? r2 : NT - 1;

        unsigned qa[2][4];
        const __half* q1p = baseh + (size_t)r1c * (3 * D) + h * DH;
        const __half* q2p = baseh + (size_t)r2c * (3 * D) + h * DH;
#pragma unroll
        for (int kk = 0; kk < 2; kk++) {
            qa[kk][0] = *(const unsigned*)(q1p + kk * 16 + 2 * t);
            qa[kk][1] = *(const unsigned*)(q2p + kk * 16 + 2 * t);
            qa[kk][2] = *(const unsigned*)(q1p + kk * 16 + 2 * t + 8);
            qa[kk][3] = *(const unsigned*)(q2p + kk * 16 + 2 * t + 8);
        }

        float o[4][4];
#pragma unroll
        for (int ct = 0; ct < 4; ct++)
#pragma unroll
            for (int i = 0; i < 4; i++) o[ct][i] = 0.0f;
        float l1 = 0.0f, l2 = 0.0f;

        const __half* b1p = bh + (size_t)r1c * NTB;
        const __half* b2p = bh + (size_t)r2c * NTB;

        for (int cc = 0; cc < 22; cc++) {
            const int j0 = cc * 16;

            // ---- QK^T: 16x16 S chunk, 4 mmas ----
            float s0[4] = {0, 0, 0, 0}, s1[4] = {0, 0, 0, 0};
#pragma unroll
            for (int kk = 0; kk < 2; kk++) {
                unsigned b0a = *(const unsigned*)&ks[(j0 + g)     * LDKH + kk * 16 + 2 * t];
                unsigned b0b = *(const unsigned*)&ks[(j0 + g)     * LDKH + kk * 16 + 2 * t + 8];
                unsigned b1a = *(const unsigned*)&ks[(j0 + 8 + g) * LDKH + kk * 16 + 2 * t];
                unsigned b1b = *(const unsigned*)&ks[(j0 + 8 + g) * LDKH + kk * 16 + 2 * t + 8];
                mma16(s0, qa[kk], b0a, b0b);
                mma16(s1, qa[kk], b1a, b1b);
            }

            // ---- bias (half2 loads) + exp ----
            const int c0 = j0 + 2 * t;
            float2 b1a = __half22float2(*(const __half2*)(b1p + c0));
            float2 b1b = __half22float2(*(const __half2*)(b1p + c0 + 8));
            float2 b2a = __half22float2(*(const __half2*)(b2p + c0));
            float2 b2b = __half22float2(*(const __half2*)(b2p + c0 + 8));

            float p1[4], p2[4];
            p1[0] = (c0     < NT) ? __expf(fmaf(s0[0], scale, b1a.x)) : 0.0f;
            p1[1] = (c0 + 1 < NT) ? __expf(fmaf(s0[1], scale, b1a.y)) : 0.0f;
            p1[2] = (c0 + 8 < NT) ? __expf(fmaf(s1[0], scale, b1b.x)) : 0.0f;
            p1[3] = (c0 + 9 < NT) ? __expf(fmaf(s1[1], scale, b1b.y)) : 0.0f;
            p2[0] = (c0     < NT) ? __expf(fmaf(s0[2], scale, b2a.x)) : 0.0f;
            p2[1] = (c0 + 1 < NT) ? __expf(fmaf(s0[3], scale, b2a.y)) : 0.0f;
            p2[2] = (c0 + 8 < NT) ? __expf(fmaf(s1[2], scale, b2b.x)) : 0.0f;
            p2[3] = (c0 + 9 < NT) ? __expf(fmaf(s1[3], scale, b2b.y)) : 0.0f;

            l1 += p1[0] + p1[1] + p1[2] + p1[3];
            l2 += p2[0] + p2[1] + p2[2] + p2[3];

            // ---- publish P chunk as half2 (4 STS.32) ----
            *(__half2*)&pw[g * LDPH + 2 * t]           = __floats2half2_rn(p1[0], p1[1]);
            *(__half2*)&pw[g * LDPH + 2 * t + 8]       = __floats2half2_rn(p1[2], p1[3]);
            *(__half2*)&pw[(g + 8) * LDPH + 2 * t]     = __floats2half2_rn(p2[0], p2[1]);
            *(__half2*)&pw[(g + 8) * LDPH + 2 * t + 8] = __floats2half2_rn(p2[2], p2[3]);
            __syncwarp();

            // ---- PV: k16 = whole chunk, 4 mmas ----
            unsigned pa[4];
            pa[0] = *(const unsigned*)&pw[g * LDPH + 2 * t];
            pa[1] = *(const unsigned*)&pw[(g + 8) * LDPH + 2 * t];
            pa[2] = *(const unsigned*)&pw[g * LDPH + 2 * t + 8];
            pa[3] = *(const unsigned*)&pw[(g + 8) * LDPH + 2 * t + 8];
#pragma unroll
            for (int ct = 0; ct < 4; ct++) {
                unsigned b0 = *(const unsigned*)&vt[(ct * 8 + g) * LDVH + j0 + 2 * t];
                unsigned b1 = *(const unsigned*)&vt[(ct * 8 + g) * LDVH + j0 + 2 * t + 8];
                mma16(o[ct], pa, b0, b1);
            }
            __syncwarp();
        }

        l1 += __shfl_xor_sync(0xffffffffu, l1, 1);
        l1 += __shfl_xor_sync(0xffffffffu, l1, 2);
        l2 += __shfl_xor_sync(0xffffffffu, l2, 1);
        l2 += __shfl_xor_sync(0xffffffffu, l2, 2);
        const float inv1 = 1.0f / l1;
        const float inv2 = 1.0f / l2;

        if (r1 < NT) {
            __half* c1 = g_ctxh + ((size_t)win * NT + r1) * D + h * DH;
#pragma unroll
            for (int ct = 0; ct < 4; ct++)
                *(__half2*)(c1 + ct * 8 + 2 * t) =
                    __floats2half2_rn(o[ct][0] * inv1, o[ct][1] * inv1);
        }
        if (r2 < NT) {
            __half* c2 = g_ctxh + ((size_t)win * NT + r2) * D + h * DH;
#pragma unroll
            for (int ct = 0; ct < 4; ct++)
                *(__half2*)(c2 + ct * 8 + 2 * t) =
                    __floats2half2_rn(o[ct][2] * inv2, o[ct][3] * inv2);
        }
    }
}

// ---------------------------------------------------------------------------
// launch
// ---------------------------------------------------------------------------
extern "C" void kernel_launch(void* const* d_in, const int* in_sizes, int n_in,
                              void* d_out, int out_size) {
    const float* x     = (const float*)d_in[0];
    const float* w_qkv = (const float*)d_in[1];
    const float* w_out = (const float*)d_in[2];
    const float* table = (const float*)d_in[3];
    float* out = (float*)d_out;

    const int attn_smem = (NTP * LDKH + 32 * LDVH + AWARPS * 16 * LDPH)
                          * (int)sizeof(__half);
    static int configured = -1;
    if (configured < 0) {
        cudaFuncSetAttribute(attn_kernel,
                             cudaFuncAttributeMaxDynamicSharedMemorySize, attn_smem);
        configured = 1;
    }

    {
        prep_kernel<<<PREP_GRID, 256>>>((const float4*)x, w_qkv, w_out, table);
    }
    {
        dim3 grid(3 * D / 128, (NWIN * NT) / 128);   // (6, 343)
        k_gemm_qkv<<<grid, 256>>>();
    }
    {
        dim3 grid(NWIN, H);
        attn_kernel<<<grid, ATHREADS, attn_smem>>>();
    }
    {
        dim3 grid(D / 128, (NWIN * NT) / 128);       // (2, 343)
        k_gemm_out<<<grid, 256>>>(out);
    }
}

// round 15
// speedup vs baseline: 1.5248x; 1.0016x over previous
#include <cuda_runtime.h>
#include <cuda_fp16.h>
#include <cstdint>

// ---------------------------------------------------------------------------
// MaxViT3D MHSA (round 15): fp16 mma pipeline.
//   vs round 14 (254.4us): GEMM cp.async pipeline deepened 2 -> 3 stages
//   (wait_group 1 keeps a tile in flight during compute; dynamic smem ring).
//   Attention + prep byte-identical to round 14.
// ---------------------------------------------------------------------------

#define NWIN 128
#define NT   343
#define NTP  352
#define NTB  352
#define D    256
#define H    8
#define DH   32

// scratch
__device__ __half g_qkvh  [(size_t)NWIN * NT * (3 * D)];
__device__ __half g_ctxh  [(size_t)NWIN * NT * D];
__device__ __half g_xh    [(size_t)NWIN * NT * D];
__device__ __half g_wqkvTh[(size_t)(3 * D) * D];   // W_qkv^T [768][256] K-major
__device__ __half g_woutTh[(size_t)D * D];         // W_out^T [256][256] K-major
__device__ __half g_biash [(size_t)H * NT * NTB];

// ---------------------------------------------------------------------------
// helpers
// ---------------------------------------------------------------------------
__device__ __forceinline__ void mma16(float* c, const unsigned* a,
                                      unsigned b0, unsigned b1) {
    asm volatile(
        "mma.sync.aligned.m16n8k16.row.col.f32.f16.f16.f32 "
        "{%0,%1,%2,%3},{%4,%5,%6,%7},{%8,%9},{%0,%1,%2,%3};"
        : "+f"(c[0]), "+f"(c[1]), "+f"(c[2]), "+f"(c[3])
        : "r"(a[0]), "r"(a[1]), "r"(a[2]), "r"(a[3]), "r"(b0), "r"(b1));
}

__device__ __forceinline__ unsigned smem_u32(const void* p) {
    unsigned r;
    asm("{.reg .u64 t; cvta.to.shared.u64 t, %1; cvt.u32.u64 %0, t;}"
        : "=r"(r) : "l"(p));
    return r;
}

__device__ __forceinline__ void cpa16(unsigned dst, const void* src) {
    asm volatile("cp.async.ca.shared.global [%0], [%1], 16;" :: "r"(dst), "l"(src));
}
#define CP_COMMIT() asm volatile("cp.async.commit_group;")

// ---------------------------------------------------------------------------
// fused prep kernel (unchanged from round 14)
// ---------------------------------------------------------------------------
#define PREP_XB 10976
#define PREP_QB 768
#define PREP_OB 256
#define PREP_BB 3773
#define PREP_GRID (PREP_XB + PREP_QB + PREP_OB + PREP_BB)

__global__ void prep_kernel(const float4* __restrict__ x,
                            const float* __restrict__ wqkv,
                            const float* __restrict__ wout,
                            const float* __restrict__ table) {
    const int b = blockIdx.x;
    if (b < PREP_XB) {
        int i = b * 256 + threadIdx.x;
        float4 v = x[i];
        __half2 h0 = __floats2half2_rn(v.x, v.y);
        __half2 h1 = __floats2half2_rn(v.z, v.w);
        ((uint2*)g_xh)[i] = make_uint2(*(unsigned*)&h0, *(unsigned*)&h1);
    } else if (b < PREP_XB + PREP_QB) {
        int idx = (b - PREP_XB) * 256 + threadIdx.x;
        int n = idx >> 8, k = idx & 255;
        g_wqkvTh[idx] = __float2half_rn(wqkv[k * (3 * D) + n]);
    } else if (b < PREP_XB + PREP_QB + PREP_OB) {
        int idx = (b - PREP_XB - PREP_QB) * 256 + threadIdx.x;
        int n = idx >> 8, k = idx & 255;
        g_woutTh[idx] = __float2half_rn(wout[k * D + n]);
    } else {
        int idx = (b - PREP_XB - PREP_QB - PREP_OB) * 256 + threadIdx.x;
        int h = idx / (NT * NTB);
        int r = idx - h * (NT * NTB);
        int i = r / NTB;
        int j = r - i * NTB;
        float v = 0.0f;
        if (j < NT) {
            int i1 = i / 49, i2 = (i / 7) % 7, i3 = i % 7;
            int j1 = j / 49, j2 = (j / 7) % 7, j3 = j % 7;
            int rel = ((i1 - j1 + 6) * 13 + (i2 - j2 + 6)) * 13 + (i3 - j3 + 6);
            v = table[rel * H + h];
        }
        g_biash[idx] = __float2half_rn(v);
    }
}

// ---------------------------------------------------------------------------
// fp16 GEMM: 128x128 tile, BK=32, 3-stage cp.async ring (dynamic smem)
// ---------------------------------------------------------------------------
#define LGH 40                       // smem row stride in halfs
#define GBUF (128 * LGH)             // halfs per tile buffer
#define GEMM_SMEM (3 * 2 * GBUF * 2) // bytes: 3 stages x (A+B) x 2B

__device__ __forceinline__ void stage32(unsigned dstBase,
                                        const __half* __restrict__ gsrc) {
    const int tid = threadIdx.x;
#pragma unroll
    for (int i = 0; i < 2; i++) {
        int id  = tid + i * 256;
        int row = id >> 2;
        int gc  = (id & 3) * 8;            // 8 halfs = 16B granule
        cpa16(dstBase + (unsigned)(row * LGH + gc) * 2,
              gsrc + (size_t)row * 256 + gc);
    }
}

template <bool HALF_OUT>
__device__ __forceinline__ void fp16_gemm_body(const __half* __restrict__ Ag,
                                               const __half* __restrict__ Bg,
                                               float* __restrict__ Cf,
                                               __half* __restrict__ Ch,
                                               int Ngl) {
    extern __shared__ __half gsm[];
    __half* As = gsm;                      // 3 x GBUF
    __half* Bs = gsm + 3 * GBUF;           // 3 x GBUF

    const int tid  = threadIdx.x;
    const int warp = tid >> 5, lane = tid & 31;
    const int g = lane >> 2, t = lane & 3;
    const int wm = warp >> 2, wn = warp & 3;

    const int rowBase = blockIdx.y * 128;
    const int colBase = blockIdx.x * 128;

    const __half* Ab = Ag + (size_t)rowBase * 256;
    const __half* Bb = Bg + (size_t)colBase * 256;

    const unsigned asb = smem_u32(As);
    const unsigned bsb = smem_u32(Bs);
    const unsigned bufBytes = GBUF * 2;

    float acc[4][4][4];
#pragma unroll
    for (int mt = 0; mt < 4; mt++)
#pragma unroll
        for (int nt = 0; nt < 4; nt++)
#pragma unroll
            for (int i = 0; i < 4; i++) acc[mt][nt][i] = 0.0f;

    // prologue: stage tiles 0 and 1 as separate groups
    stage32(asb, Ab);
    stage32(bsb, Bb);
    CP_COMMIT();
    stage32(asb + bufBytes, Ab + 32);
    stage32(bsb + bufBytes, Bb + 32);
    CP_COMMIT();

    const int iters = 256 / 32;   // 8
#pragma unroll
    for (int it = 0; it < iters; it++) {
        // two groups outstanding except on the final iteration
        if (it == iters - 1) asm volatile("cp.async.wait_group 0;" ::: "memory");
        else                 asm volatile("cp.async.wait_group 1;" ::: "memory");
        __syncthreads();
        if (it + 2 < iters) {
            int nb = (it + 2) % 3;
            stage32(asb + nb * bufBytes, Ab + (it + 2) * 32);
            stage32(bsb + nb * bufBytes, Bb + (it + 2) * 32);
            CP_COMMIT();
        }
        const __half* Abs = As + (it % 3) * GBUF;
        const __half* Bbs = Bs + (it % 3) * GBUF;

#pragma unroll
        for (int ks = 0; ks < 32; ks += 16) {
            unsigned a[4][4], b[4][2];
#pragma unroll
            for (int mt = 0; mt < 4; mt++) {
                int r = wm * 64 + mt * 16;
                a[mt][0] = *(const unsigned*)&Abs[(r + g)     * LGH + ks + 2 * t];
                a[mt][1] = *(const unsigned*)&Abs[(r + g + 8) * LGH + ks + 2 * t];
                a[mt][2] = *(const unsigned*)&Abs[(r + g)     * LGH + ks + 2 * t + 8];
                a[mt][3] = *(const unsigned*)&Abs[(r + g + 8) * LGH + ks + 2 * t + 8];
            }
#pragma unroll
            for (int nt = 0; nt < 4; nt++) {
                int cb = wn * 32 + nt * 8;
                b[nt][0] = *(const unsigned*)&Bbs[(cb + g) * LGH + ks + 2 * t];
                b[nt][1] = *(const unsigned*)&Bbs[(cb + g) * LGH + ks + 2 * t + 8];
            }
#pragma unroll
            for (int mt = 0; mt < 4; mt++)
#pragma unroll
                for (int nt = 0; nt < 4; nt++)
                    mma16(acc[mt][nt], a[mt], b[nt][0], b[nt][1]);
        }
    }

#pragma unroll
    for (int mt = 0; mt < 4; mt++) {
#pragma unroll
        for (int nt = 0; nt < 4; nt++) {
            int r = rowBase + wm * 64 + mt * 16 + g;
            int c = colBase + wn * 32 + nt * 8 + 2 * t;
            if (HALF_OUT) {
                __half2 h0 = __floats2half2_rn(acc[mt][nt][0], acc[mt][nt][1]);
                __half2 h1 = __floats2half2_rn(acc[mt][nt][2], acc[mt][nt][3]);
                *(__half2*)(Ch + (size_t)r * Ngl + c)       = h0;
                *(__half2*)(Ch + (size_t)(r + 8) * Ngl + c) = h1;
            } else {
                *(float2*)(Cf + (size_t)r * Ngl + c) =
                    make_float2(acc[mt][nt][0], acc[mt][nt][1]);
                *(float2*)(Cf + (size_t)(r + 8) * Ngl + c) =
                    make_float2(acc[mt][nt][2], acc[mt][nt][3]);
            }
        }
    }
}

__global__ __launch_bounds__(256)
void k_gemm_qkv() {
    fp16_gemm_body<true>(g_xh, g_wqkvTh, nullptr, g_qkvh, 3 * D);
}

__global__ __launch_bounds__(256)
void k_gemm_out(float* __restrict__ out) {
    fp16_gemm_body<false>(g_ctxh, g_woutTh, out, nullptr, D);
}

// ---------------------------------------------------------------------------
// attention (EXACT round-14 body)
// ---------------------------------------------------------------------------
#define LDKH 40
#define LDVH 360
#define LDPH 24
#define AWARPS 11
#define ATHREADS (AWARPS * 32)

__global__ __launch_bounds__(ATHREADS)
void attn_kernel() {
    const int win = blockIdx.x;
    const int h   = blockIdx.y;

    extern __shared__ __half smh[];
    __half* ks = smh;                         // NTP*LDKH
    __half* vt = ks + NTP * LDKH;             // 32*LDVH
    __half* pb = vt + 32 * LDVH;              // AWARPS*16*LDPH

    const int tid  = threadIdx.x;
    const int warp = tid >> 5, lane = tid & 31;
    const int g = lane >> 2, t = lane & 3;

    const __half* baseh = g_qkvh + (size_t)win * NT * (3 * D);

    for (int idx = tid; idx < NTP * DH; idx += ATHREADS) {
        int j = idx >> 5, c = idx & 31;
        __half kv = __float2half_rn(0.0f), vv = kv;
        if (j < NT) {
            const __half* row = baseh + (size_t)j * (3 * D) + h * DH;
            kv = row[D + c];
            vv = row[2 * D + c];
        }
        ks[j * LDKH + c] = kv;
        vt[c * LDVH + j] = vv;
    }
    __syncthreads();

    const float scale = 0.17677669529663687f;
    const __half* bh = g_biash + (size_t)h * NT * NTB;
    __half* pw = pb + warp * 16 * LDPH;

    for (int qt = warp; qt < 22; qt += AWARPS) {
        const int i0 = qt * 16;
        const int r1 = i0 + g, r2 = r1 + 8;
        const int r1c = r1 < NT ? r1 : NT - 1;
        const int r2c = r2 < NT ? r2 : NT - 1;

        unsigned qa[2][4];
        const __half* q1p = baseh + (size_t)r1c * (3 * D) + h * DH;
        const __half* q2p = baseh + (size_t)r2c * (3 * D) + h * DH;
#pragma unroll
        for (int kk = 0; kk < 2; kk++) {
            qa[kk][0] = *(const unsigned*)(q1p + kk * 16 + 2 * t);
            qa[kk][1] = *(const unsigned*)(q2p + kk * 16 + 2 * t);
            qa[kk][2] = *(const unsigned*)(q1p + kk * 16 + 2 * t + 8);
            qa[kk][3] = *(const unsigned*)(q2p + kk * 16 + 2 * t + 8);
        }

        float o[4][4];
#pragma unroll
        for (int ct = 0; ct < 4; ct++)
#pragma unroll
            for (int i = 0; i < 4; i++) o[ct][i] = 0.0f;
        float l1 = 0.0f, l2 = 0.0f;

        const __half* b1p = bh + (size_t)r1c * NTB;
        const __half* b2p = bh + (size_t)r2c * NTB;

        for (int cc = 0; cc < 22; cc++) {
            const int j0 = cc * 16;

            float s0[4] = {0, 0, 0, 0}, s1[4] = {0, 0, 0, 0};
#pragma unroll
            for (int kk = 0; kk < 2; kk++) {
                unsigned b0a = *(const unsigned*)&ks[(j0 + g)     * LDKH + kk * 16 + 2 * t];
                unsigned b0b = *(const unsigned*)&ks[(j0 + g)     * LDKH + kk * 16 + 2 * t + 8];
                unsigned b1a = *(const unsigned*)&ks[(j0 + 8 + g) * LDKH + kk * 16 + 2 * t];
                unsigned b1b = *(const unsigned*)&ks[(j0 + 8 + g) * LDKH + kk * 16 + 2 * t + 8];
                mma16(s0, qa[kk], b0a, b0b);
                mma16(s1, qa[kk], b1a, b1b);
            }

            const int c0 = j0 + 2 * t;
            float2 b1a = __half22float2(*(const __half2*)(b1p + c0));
            float2 b1b = __half22float2(*(const __half2*)(b1p + c0 + 8));
            float2 b2a = __half22float2(*(const __half2*)(b2p + c0));
            float2 b2b = __half22float2(*(const __half2*)(b2p + c0 + 8));

            float p1[4], p2[4];
            p1[0] = (c0     < NT) ? __expf(fmaf(s0[0], scale, b1a.x)) : 0.0f;
            p1[1] = (c0 + 1 < NT) ? __expf(fmaf(s0[1], scale, b1a.y)) : 0.0f;
            p1[2] = (c0 + 8 < NT) ? __expf(fmaf(s1[0], scale, b1b.x)) : 0.0f;
            p1[3] = (c0 + 9 < NT) ? __expf(fmaf(s1[1], scale, b1b.y)) : 0.0f;
            p2[0] = (c0     < NT) ? __expf(fmaf(s0[2], scale, b2a.x)) : 0.0f;
            p2[1] = (c0 + 1 < NT) ? __expf(fmaf(s0[3], scale, b2a.y)) : 0.0f;
            p2[2] = (c0 + 8 < NT) ? __expf(fmaf(s1[2], scale, b2b.x)) : 0.0f;
            p2[3] = (c0 + 9 < NT) ? __expf(fmaf(s1[3], scale, b2b.y)) : 0.0f;

            l1 += p1[0] + p1[1] + p1[2] + p1[3];
            l2 += p2[0] + p2[1] + p2[2] + p2[3];

            *(__half2*)&pw[g * LDPH + 2 * t]           = __floats2half2_rn(p1[0], p1[1]);
            *(__half2*)&pw[g * LDPH + 2 * t + 8]       = __floats2half2_rn(p1[2], p1[3]);
            *(__half2*)&pw[(g + 8) * LDPH + 2 * t]     = __floats2half2_rn(p2[0], p2[1]);
            *(__half2*)&pw[(g + 8) * LDPH + 2 * t + 8] = __floats2half2_rn(p2[2], p2[3]);
            __syncwarp();

            unsigned pa[4];
            pa[0] = *(const unsigned*)&pw[g * LDPH + 2 * t];
            pa[1] = *(const unsigned*)&pw[(g + 8) * LDPH + 2 * t];
            pa[2] = *(const unsigned*)&pw[g * LDPH + 2 * t + 8];
            pa[3] = *(const unsigned*)&pw[(g + 8) * LDPH + 2 * t + 8];
#pragma unroll
            for (int ct = 0; ct < 4; ct++) {
                unsigned b0 = *(const unsigned*)&vt[(ct * 8 + g) * LDVH + j0 + 2 * t];
                unsigned b1 = *(const unsigned*)&vt[(ct * 8 + g) * LDVH + j0 + 2 * t + 8];
                mma16(o[ct], pa, b0, b1);
            }
            __syncwarp();
        }

        l1 += __shfl_xor_sync(0xffffffffu, l1, 1);
        l1 += __shfl_xor_sync(0xffffffffu, l1, 2);
        l2 += __shfl_xor_sync(0xffffffffu, l2, 1);
        l2 += __shfl_xor_sync(0xffffffffu, l2, 2);
        const float inv1 = 1.0f / l1;
        const float inv2 = 1.0f / l2;

        if (r1 < NT) {
            __half* c1 = g_ctxh + ((size_t)win * NT + r1) * D + h * DH;
#pragma unroll
            for (int ct = 0; ct < 4; ct++)
                *(__half2*)(c1 + ct * 8 + 2 * t) =
                    __floats2half2_rn(o[ct][0] * inv1, o[ct][1] * inv1);
        }
        if (r2 < NT) {
            __half* c2 = g_ctxh + ((size_t)win * NT + r2) * D + h * DH;
#pragma unroll
            for (int ct = 0; ct < 4; ct++)
                *(__half2*)(c2 + ct * 8 + 2 * t) =
                    __floats2half2_rn(o[ct][2] * inv2, o[ct][3] * inv2);
        }
    }
}

// ---------------------------------------------------------------------------
// launch
// ---------------------------------------------------------------------------
extern "C" void kernel_launch(void* const* d_in, const int* in_sizes, int n_in,
                              void* d_out, int out_size) {
    const float* x     = (const float*)d_in[0];
    const float* w_qkv = (const float*)d_in[1];
    const float* w_out = (const float*)d_in[2];
    const float* table = (const float*)d_in[3];
    float* out = (float*)d_out;

    const int attn_smem = (NTP * LDKH + 32 * LDVH + AWARPS * 16 * LDPH)
                          * (int)sizeof(__half);
    static int configured = -1;
    if (configured < 0) {
        cudaFuncSetAttribute(attn_kernel,
                             cudaFuncAttributeMaxDynamicSharedMemorySize, attn_smem);
        cudaFuncSetAttribute(k_gemm_qkv,
                             cudaFuncAttributeMaxDynamicSharedMemorySize, GEMM_SMEM);
        cudaFuncSetAttribute(k_gemm_out,
                             cudaFuncAttributeMaxDynamicSharedMemorySize, GEMM_SMEM);
        configured = 1;
    }

    {
        prep_kernel<<<PREP_GRID, 256>>>((const float4*)x, w_qkv, w_out, table);
    }
    {
        dim3 grid(3 * D / 128, (NWIN * NT) / 128);   // (6, 343)
        k_gemm_qkv<<<grid, 256, GEMM_SMEM>>>();
    }
    {
        dim3 grid(NWIN, H);
        attn_kernel<<<grid, ATHREADS, attn_smem>>>();
    }
    {
        dim3 grid(D / 128, (NWIN * NT) / 128);       // (2, 343)
        k_gemm_out<<<grid, 256, GEMM_SMEM>>>(out);
    }
}

// round 16
// speedup vs baseline: 1.6410x; 1.0762x over previous
#include <cuda_runtime.h>
#include <cuda_fp16.h>
#include <cstdint>

// ---------------------------------------------------------------------------
// MaxViT3D MHSA (round 16): fp16 mma pipeline.
//   vs round 15 (254.0us): GEMM warp tile widened 64x32 -> 64x64
//   (4 warps/CTA, 2x2 grid). Fragment smem traffic drops from 192B/HMMA to
//   128B/HMMA -- the smem crossbar, not latency, is the modeled binding
//   resource (tensor% pinned ~29% across all latency-oriented changes).
//   2-stage static-smem pipeline (3-stage was neutral). Attention + prep
//   byte-identical to round 15.
// ---------------------------------------------------------------------------

#define NWIN 128
#define NT   343
#define NTP  352
#define NTB  352
#define D    256
#define H    8
#define DH   32

// scratch
__device__ __half g_qkvh  [(size_t)NWIN * NT * (3 * D)];
__device__ __half g_ctxh  [(size_t)NWIN * NT * D];
__device__ __half g_xh    [(size_t)NWIN * NT * D];
__device__ __half g_wqkvTh[(size_t)(3 * D) * D];   // W_qkv^T [768][256] K-major
__device__ __half g_woutTh[(size_t)D * D];         // W_out^T [256][256] K-major
__device__ __half g_biash [(size_t)H * NT * NTB];

// ---------------------------------------------------------------------------
// helpers
// ---------------------------------------------------------------------------
__device__ __forceinline__ void mma16(float* c, const unsigned* a,
                                      unsigned b0, unsigned b1) {
    asm volatile(
        "mma.sync.aligned.m16n8k16.row.col.f32.f16.f16.f32 "
        "{%0,%1,%2,%3},{%4,%5,%6,%7},{%8,%9},{%0,%1,%2,%3};"
        : "+f"(c[0]), "+f"(c[1]), "+f"(c[2]), "+f"(c[3])
        : "r"(a[0]), "r"(a[1]), "r"(a[2]), "r"(a[3]), "r"(b0), "r"(b1));
}

__device__ __forceinline__ unsigned smem_u32(const void* p) {
    unsigned r;
    asm("{.reg .u64 t; cvta.to.shared.u64 t, %1; cvt.u32.u64 %0, t;}"
        : "=r"(r) : "l"(p));
    return r;
}

__device__ __forceinline__ void cpa16(unsigned dst, const void* src) {
    asm volatile("cp.async.ca.shared.global [%0], [%1], 16;" :: "r"(dst), "l"(src));
}
#define CP_COMMIT() asm volatile("cp.async.commit_group;")

// ---------------------------------------------------------------------------
// fused prep kernel (unchanged from round 14/15)
// ---------------------------------------------------------------------------
#define PREP_XB 10976
#define PREP_QB 768
#define PREP_OB 256
#define PREP_BB 3773
#define PREP_GRID (PREP_XB + PREP_QB + PREP_OB + PREP_BB)

__global__ void prep_kernel(const float4* __restrict__ x,
                            const float* __restrict__ wqkv,
                            const float* __restrict__ wout,
                            const float* __restrict__ table) {
    const int b = blockIdx.x;
    if (b < PREP_XB) {
        int i = b * 256 + threadIdx.x;
        float4 v = x[i];
        __half2 h0 = __floats2half2_rn(v.x, v.y);
        __half2 h1 = __floats2half2_rn(v.z, v.w);
        ((uint2*)g_xh)[i] = make_uint2(*(unsigned*)&h0, *(unsigned*)&h1);
    } else if (b < PREP_XB + PREP_QB) {
        int idx = (b - PREP_XB) * 256 + threadIdx.x;
        int n = idx >> 8, k = idx & 255;
        g_wqkvTh[idx] = __float2half_rn(wqkv[k * (3 * D) + n]);
    } else if (b < PREP_XB + PREP_QB + PREP_OB) {
        int idx = (b - PREP_XB - PREP_QB) * 256 + threadIdx.x;
        int n = idx >> 8, k = idx & 255;
        g_woutTh[idx] = __float2half_rn(wout[k * D + n]);
    } else {
        int idx = (b - PREP_XB - PREP_QB - PREP_OB) * 256 + threadIdx.x;
        int h = idx / (NT * NTB);
        int r = idx - h * (NT * NTB);
        int i = r / NTB;
        int j = r - i * NTB;
        float v = 0.0f;
        if (j < NT) {
            int i1 = i / 49, i2 = (i / 7) % 7, i3 = i % 7;
            int j1 = j / 49, j2 = (j / 7) % 7, j3 = j % 7;
            int rel = ((i1 - j1 + 6) * 13 + (i2 - j2 + 6)) * 13 + (i3 - j3 + 6);
            v = table[rel * H + h];
        }
        g_biash[idx] = __float2half_rn(v);
    }
}

// ---------------------------------------------------------------------------
// fp16 GEMM: 128x128 CTA tile, 4 warps of 64x64 (2x2 grid), BK=32,
// 2-stage cp.async, static smem. 128 threads.
// ---------------------------------------------------------------------------
#define LGH 40   // smem row stride in halfs

__device__ __forceinline__ void stage32_128(unsigned dstBase,
                                            const __half* __restrict__ gsrc) {
    const int tid = threadIdx.x;   // 128 threads
#pragma unroll
    for (int i = 0; i < 4; i++) {
        int id  = tid + i * 128;
        int row = id >> 2;
        int gc  = (id & 3) * 8;            // 8 halfs = 16B granule
        cpa16(dstBase + (unsigned)(row * LGH + gc) * 2,
              gsrc + (size_t)row * 256 + gc);
    }
}

template <bool HALF_OUT>
__device__ __forceinline__ void fp16_gemm_body(const __half* __restrict__ Ag,
                                               const __half* __restrict__ Bg,
                                               float* __restrict__ Cf,
                                               __half* __restrict__ Ch,
                                               int Ngl) {
    __shared__ __half As[2][128 * LGH];
    __shared__ __half Bs[2][128 * LGH];

    const int tid  = threadIdx.x;
    const int warp = tid >> 5, lane = tid & 31;
    const int g = lane >> 2, t = lane & 3;
    const int wm = warp >> 1, wn = warp & 1;    // 2x2 warp grid, 64x64 tiles

    const int rowBase = blockIdx.y * 128;
    const int colBase = blockIdx.x * 128;

    const __half* Ab = Ag + (size_t)rowBase * 256;
    const __half* Bb = Bg + (size_t)colBase * 256;

    const unsigned asb0 = smem_u32(&As[0][0]);
    const unsigned bsb0 = smem_u32(&Bs[0][0]);
    const unsigned bufBytes = 128 * LGH * 2;

    float acc[4][8][4];
#pragma unroll
    for (int mt = 0; mt < 4; mt++)
#pragma unroll
        for (int nt = 0; nt < 8; nt++)
#pragma unroll
            for (int i = 0; i < 4; i++) acc[mt][nt][i] = 0.0f;

    stage32_128(asb0, Ab);
    stage32_128(bsb0, Bb);
    CP_COMMIT();

    const int iters = 256 / 32;   // 8
    for (int it = 0; it < iters; it++) {
        asm volatile("cp.async.wait_group 0;" ::: "memory");
        __syncthreads();
        if (it + 1 < iters) {
            int nb = (it + 1) & 1;
            stage32_128(asb0 + nb * bufBytes, Ab + (it + 1) * 32);
            stage32_128(bsb0 + nb * bufBytes, Bb + (it + 1) * 32);
            CP_COMMIT();
        }
        const __half* Abs = As[it & 1];
        const __half* Bbs = Bs[it & 1];

#pragma unroll
        for (int ks = 0; ks < 32; ks += 16) {
            unsigned a[4][4], b[8][2];
#pragma unroll
            for (int mt = 0; mt < 4; mt++) {
                int r = wm * 64 + mt * 16;
                a[mt][0] = *(const unsigned*)&Abs[(r + g)     * LGH + ks + 2 * t];
                a[mt][1] = *(const unsigned*)&Abs[(r + g + 8) * LGH + ks + 2 * t];
                a[mt][2] = *(const unsigned*)&Abs[(r + g)     * LGH + ks + 2 * t + 8];
                a[mt][3] = *(const unsigned*)&Abs[(r + g + 8) * LGH + ks + 2 * t + 8];
            }
#pragma unroll
            for (int nt = 0; nt < 8; nt++) {
                int cb = wn * 64 + nt * 8;
                b[nt][0] = *(const unsigned*)&Bbs[(cb + g) * LGH + ks + 2 * t];
                b[nt][1] = *(const unsigned*)&Bbs[(cb + g) * LGH + ks + 2 * t + 8];
            }
#pragma unroll
            for (int mt = 0; mt < 4; mt++)
#pragma unroll
                for (int nt = 0; nt < 8; nt++)
                    mma16(acc[mt][nt], a[mt], b[nt][0], b[nt][1]);
        }
    }

#pragma unroll
    for (int mt = 0; mt < 4; mt++) {
#pragma unroll
        for (int nt = 0; nt < 8; nt++) {
            int r = rowBase + wm * 64 + mt * 16 + g;
            int c = colBase + wn * 64 + nt * 8 + 2 * t;
            if (HALF_OUT) {
                __half2 h0 = __floats2half2_rn(acc[mt][nt][0], acc[mt][nt][1]);
                __half2 h1 = __floats2half2_rn(acc[mt][nt][2], acc[mt][nt][3]);
                *(__half2*)(Ch + (size_t)r * Ngl + c)       = h0;
                *(__half2*)(Ch + (size_t)(r + 8) * Ngl + c) = h1;
            } else {
                *(float2*)(Cf + (size_t)r * Ngl + c) =
                    make_float2(acc[mt][nt][0], acc[mt][nt][1]);
                *(float2*)(Cf + (size_t)(r + 8) * Ngl + c) =
                    make_float2(acc[mt][nt][2], acc[mt][nt][3]);
            }
        }
    }
}

__global__ __launch_bounds__(128)
void k_gemm_qkv() {
    fp16_gemm_body<true>(g_xh, g_wqkvTh, nullptr, g_qkvh, 3 * D);
}

__global__ __launch_bounds__(128)
void k_gemm_out(float* __restrict__ out) {
    fp16_gemm_body<false>(g_ctxh, g_woutTh, out, nullptr, D);
}

// ---------------------------------------------------------------------------
// attention (EXACT round-14/15 body)
// ---------------------------------------------------------------------------
#define LDKH 40
#define LDVH 360
#define LDPH 24
#define AWARPS 11
#define ATHREADS (AWARPS * 32)

__global__ __launch_bounds__(ATHREADS)
void attn_kernel() {
    const int win = blockIdx.x;
    const int h   = blockIdx.y;

    extern __shared__ __half smh[];
    __half* ks = smh;                         // NTP*LDKH
    __half* vt = ks + NTP * LDKH;             // 32*LDVH
    __half* pb = vt + 32 * LDVH;              // AWARPS*16*LDPH

    const int tid  = threadIdx.x;
    const int warp = tid >> 5, lane = tid & 31;
    const int g = lane >> 2, t = lane & 3;

    const __half* baseh = g_qkvh + (size_t)win * NT * (3 * D);

    for (int idx = tid; idx < NTP * DH; idx += ATHREADS) {
        int j = idx >> 5, c = idx & 31;
        __half kv = __float2half_rn(0.0f), vv = kv;
        if (j < NT) {
            const __half* row = baseh + (size_t)j * (3 * D) + h * DH;
            kv = row[D + c];
            vv = row[2 * D + c];
        }
        ks[j * LDKH + c] = kv;
        vt[c * LDVH + j] = vv;
    }
    __syncthreads();

    const float scale = 0.17677669529663687f;
    const __half* bh = g_biash + (size_t)h * NT * NTB;
    __half* pw = pb + warp * 16 * LDPH;

    for (int qt = warp; qt < 22; qt += AWARPS) {
        const int i0 = qt * 16;
        const int r1 = i0 + g, r2 = r1 + 8;
        const int r1c = r1 < NT ? r1 : NT - 1;
        const int r2c = r2 < NT ? r2 : NT - 1;

        unsigned qa[2][4];
        const __half* q1p = baseh + (size_t)r1c * (3 * D) + h * DH;
        const __half* q2p = baseh + (size_t)r2c * (3 * D) + h * DH;
#pragma unroll
        for (int kk = 0; kk < 2; kk++) {
            qa[kk][0] = *(const unsigned*)(q1p + kk * 16 + 2 * t);
            qa[kk][1] = *(const unsigned*)(q2p + kk * 16 + 2 * t);
            qa[kk][2] = *(const unsigned*)(q1p + kk * 16 + 2 * t + 8);
            qa[kk][3] = *(const unsigned*)(q2p + kk * 16 + 2 * t + 8);
        }

        float o[4][4];
#pragma unroll
        for (int ct = 0; ct < 4; ct++)
#pragma unroll
            for (int i = 0; i < 4; i++) o[ct][i] = 0.0f;
        float l1 = 0.0f, l2 = 0.0f;

        const __half* b1p = bh + (size_t)r1c * NTB;
        const __half* b2p = bh + (size_t)r2c * NTB;

        for (int cc = 0; cc < 22; cc++) {
            const int j0 = cc * 16;

            float s0[4] = {0, 0, 0, 0}, s1[4] = {0, 0, 0, 0};
#pragma unroll
            for (int kk = 0; kk < 2; kk++) {
                unsigned b0a = *(const unsigned*)&ks[(j0 + g)     * LDKH + kk * 16 + 2 * t];
                unsigned b0b = *(const unsigned*)&ks[(j0 + g)     * LDKH + kk * 16 + 2 * t + 8];
                unsigned b1a = *(const unsigned*)&ks[(j0 + 8 + g) * LDKH + kk * 16 + 2 * t];
                unsigned b1b = *(const unsigned*)&ks[(j0 + 8 + g) * LDKH + kk * 16 + 2 * t + 8];
                mma16(s0, qa[kk], b0a, b0b);
                mma16(s1, qa[kk], b1a, b1b);
            }

            const int c0 = j0 + 2 * t;
            float2 b1a = __half22float2(*(const __half2*)(b1p + c0));
            float2 b1b = __half22float2(*(const __half2*)(b1p + c0 + 8));
            float2 b2a = __half22float2(*(const __half2*)(b2p + c0));
            float2 b2b = __half22float2(*(const __half2*)(b2p + c0 + 8));

            float p1[4], p2[4];
            p1[0] = (c0     < NT) ? __expf(fmaf(s0[0], scale, b1a.x)) : 0.0f;
            p1[1] = (c0 + 1 < NT) ? __expf(fmaf(s0[1], scale, b1a.y)) : 0.0f;
            p1[2] = (c0 + 8 < NT) ? __expf(fmaf(s1[0], scale, b1b.x)) : 0.0f;
            p1[3] = (c0 + 9 < NT) ? __expf(fmaf(s1[1], scale, b1b.y)) : 0.0f;
            p2[0] = (c0     < NT) ? __expf(fmaf(s0[2], scale, b2a.x)) : 0.0f;
            p2[1] = (c0 + 1 < NT) ? __expf(fmaf(s0[3], scale, b2a.y)) : 0.0f;
            p2[2] = (c0 + 8 < NT) ? __expf(fmaf(s1[2], scale, b2b.x)) : 0.0f;
            p2[3] = (c0 + 9 < NT) ? __expf(fmaf(s1[3], scale, b2b.y)) : 0.0f;

            l1 += p1[0] + p1[1] + p1[2] + p1[3];
            l2 += p2[0] + p2[1] + p2[2] + p2[3];

            *(__half2*)&pw[g * LDPH + 2 * t]           = __floats2half2_rn(p1[0], p1[1]);
            *(__half2*)&pw[g * LDPH + 2 * t + 8]       = __floats2half2_rn(p1[2], p1[3]);
            *(__half2*)&pw[(g + 8) * LDPH + 2 * t]     = __floats2half2_rn(p2[0], p2[1]);
            *(__half2*)&pw[(g + 8) * LDPH + 2 * t + 8] = __floats2half2_rn(p2[2], p2[3]);
            __syncwarp();

            unsigned pa[4];
            pa[0] = *(const unsigned*)&pw[g * LDPH + 2 * t];
            pa[1] = *(const unsigned*)&pw[(g + 8) * LDPH + 2 * t];
            pa[2] = *(const unsigned*)&pw[g * LDPH + 2 * t + 8];
            pa[3] = *(const unsigned*)&pw[(g + 8) * LDPH + 2 * t + 8];
#pragma unroll
            for (int ct = 0; ct < 4; ct++) {
                unsigned b0 = *(const unsigned*)&vt[(ct * 8 + g) * LDVH + j0 + 2 * t];
                unsigned b1 = *(const unsigned*)&vt[(ct * 8 + g) * LDVH + j0 + 2 * t + 8];
                mma16(o[ct], pa, b0, b1);
            }
            __syncwarp();
        }

        l1 += __shfl_xor_sync(0xffffffffu, l1, 1);
        l1 += __shfl_xor_sync(0xffffffffu, l1, 2);
        l2 += __shfl_xor_sync(0xffffffffu, l2, 1);
        l2 += __shfl_xor_sync(0xffffffffu, l2, 2);
        const float inv1 = 1.0f / l1;
        const float inv2 = 1.0f / l2;

        if (r1 < NT) {
            __half* c1 = g_ctxh + ((size_t)win * NT + r1) * D + h * DH;
#pragma unroll
            for (int ct = 0; ct < 4; ct++)
                *(__half2*)(c1 + ct * 8 + 2 * t) =
                    __floats2half2_rn(o[ct][0] * inv1, o[ct][1] * inv1);
        }
        if (r2 < NT) {
            __half* c2 = g_ctxh + ((size_t)win * NT + r2) * D + h * DH;
#pragma unroll
            for (int ct = 0; ct < 4; ct++)
                *(__half2*)(c2 + ct * 8 + 2 * t) =
                    __floats2half2_rn(o[ct][2] * inv2, o[ct][3] * inv2);
        }
    }
}

// ---------------------------------------------------------------------------
// launch
// ---------------------------------------------------------------------------
extern "C" void kernel_launch(void* const* d_in, const int* in_sizes, int n_in,
                              void* d_out, int out_size) {
    const float* x     = (const float*)d_in[0];
    const float* w_qkv = (const float*)d_in[1];
    const float* w_out = (const float*)d_in[2];
    const float* table = (const float*)d_in[3];
    float* out = (float*)d_out;

    const int attn_smem = (NTP * LDKH + 32 * LDVH + AWARPS * 16 * LDPH)
                          * (int)sizeof(__half);
    static int configured = -1;
    if (configured < 0) {
        cudaFuncSetAttribute(attn_kernel,
                             cudaFuncAttributeMaxDynamicSharedMemorySize, attn_smem);
        configured = 1;
    }

    {
        prep_kernel<<<PREP_GRID, 256>>>((const float4*)x, w_qkv, w_out, table);
    }
    {
        dim3 grid(3 * D / 128, (NWIN * NT) / 128);   // (6, 343)
        k_gemm_qkv<<<grid, 128>>>();
    }
    {
        dim3 grid(NWIN, H);
        attn_kernel<<<grid, ATHREADS, attn_smem>>>();
    }
    {
        dim3 grid(D / 128, (NWIN * NT) / 128);       // (2, 343)
        k_gemm_out<<<grid, 128>>>(out);
    }
}